// round 4
// baseline (speedup 1.0000x reference)
#include <cuda_runtime.h>

// Problem constants (fixed shapes for SpNCN_Layer_81106162417854)
#define T_STEPS 800
#define BATCH   128
#define S_DIM   500
#define BS      (BATCH * S_DIM)          // 64000
#define M_ROWS  (T_STEPS * BATCH)        // 102400

// Recurrence constants — double math rounded once to f32 (matches Python float
// -> jnp.float32 weak promotion).
#define DT     0.25
#define ALPHA_F ((float)(1.0 - DT / 10.0))
#define BETA_F  ((float)(1.0 - DT / 20.0))
#define KAPPA_F ((float)(1.0 - DT / 30.0))
#define THRESH_F 0.4f

// Scratch for total = input - error @ W^T  (205 MB, __device__ global per rules)
__device__ float g_total[(size_t)T_STEPS * BATCH * S_DIM];

// ---------------------------------------------------------------------------
// Kernel 1: total[m, n] = inp[m, n] - sum_k err[m, k] * W[n, k]
// NUMERICS CONTRACT: serial ascending-k, single-accumulator FUSED fma chain
// per output element (cuBLAS-SGEMM / Eigen-gebp order). Tiling must not
// change the chain.
// ---------------------------------------------------------------------------
#define BM 64
#define BN 64
#define BK 16

__global__ __launch_bounds__(256) void gemm_total_kernel(
    const float* __restrict__ inp,
    const float* __restrict__ err,
    const float* __restrict__ W)
{
    __shared__ float As[BK][BM + 4];   // As[k][m]
    __shared__ float Bs[BK][BN + 4];   // Bs[k][n]

    const int bm = blockIdx.y * BM;
    const int bn = blockIdx.x * BN;
    const int tid = threadIdx.x;       // 0..255
    const int tx = tid & 15;           // output col group
    const int ty = tid >> 4;           // output row group

    const int lcol = tid & 15;         // k within tile for loads
    const int lrow = tid >> 4;         // base row for loads

    float acc[4][4] = {};

    for (int k0 = 0; k0 < S_DIM; k0 += BK) {
        const int k = k0 + lcol;
        const bool kok = (k < S_DIM);
#pragma unroll
        for (int i = 0; i < 4; i++) {
            const int row = lrow + i * 16;             // 0..63
            As[lcol][row] = kok ? err[(size_t)(bm + row) * S_DIM + k] : 0.f;
            const int n = bn + row;
            Bs[lcol][row] = (kok && n < S_DIM) ? W[(size_t)n * S_DIM + k] : 0.f;
        }
        __syncthreads();

#pragma unroll
        for (int kk = 0; kk < BK; kk++) {
            float a[4], b[4];
#pragma unroll
            for (int i = 0; i < 4; i++) a[i] = As[kk][ty + 16 * i];
#pragma unroll
            for (int j = 0; j < 4; j++) b[j] = Bs[kk][tx + 16 * j];
#pragma unroll
            for (int i = 0; i < 4; i++)
#pragma unroll
                for (int j = 0; j < 4; j++)
                    acc[i][j] = __fmaf_rn(a[i], b[j], acc[i][j]);
        }
        __syncthreads();
    }

#pragma unroll
    for (int i = 0; i < 4; i++) {
        const int m = bm + ty + 16 * i;
#pragma unroll
        for (int j = 0; j < 4; j++) {
            const int n = bn + tx + 16 * j;
            if (n < S_DIM) {
                // total = input - (err @ W^T): single round-to-nearest subtract
                g_total[(size_t)m * S_DIM + n] =
                    __fadd_rn(inp[(size_t)m * S_DIM + n], -acc[i][j]);
            }
        }
    }
}

// ---------------------------------------------------------------------------
// Kernel 2: sequential scan over T for each (b, s) neuron.
//   reset = H(mem - thr); syn = fma(a, syn, tot); mem = fma(b, mem, syn)*(1-reset);
//   spk = H(mem - thr);   trace = fma(k, trace, spk)
// FUSED fma for every mul+add pair (contracted lowering); thresholds as
// (x - 0.4f) > 0 exactly like the reference's spike_fn.
// ---------------------------------------------------------------------------
__global__ __launch_bounds__(256) void scan_kernel(
    float* __restrict__ spk_out,
    float* __restrict__ tr_out)
{
    const int idx = blockIdx.x * blockDim.x + threadIdx.x;
    if (idx >= BS) return;

    const float* tp = g_total + idx;
    float* sp = spk_out + idx;
    float* rp = tr_out + idx;

    float syn = 0.f, mem = 0.f, trace = 0.f;

#pragma unroll 1
    for (int t0 = 0; t0 < T_STEPS; t0 += 8) {
        float tot[8];
#pragma unroll
        for (int i = 0; i < 8; i++)
            tot[i] = __ldcs(tp + (size_t)(t0 + i) * BS);   // streaming, MLP=8

#pragma unroll
        for (int i = 0; i < 8; i++) {
            const float reset = (__fadd_rn(mem, -THRESH_F) > 0.f) ? 1.f : 0.f;
            syn = __fmaf_rn(ALPHA_F, syn, tot[i]);
            mem = __fmul_rn(__fmaf_rn(BETA_F, mem, syn),
                            __fadd_rn(1.f, -reset));
            const float spk = (__fadd_rn(mem, -THRESH_F) > 0.f) ? 1.f : 0.f;
            trace = __fmaf_rn(KAPPA_F, trace, spk);
            __stcs(sp + (size_t)(t0 + i) * BS, spk);
            __stcs(rp + (size_t)(t0 + i) * BS, trace);
        }
    }
}

// ---------------------------------------------------------------------------
extern "C" void kernel_launch(void* const* d_in, const int* in_sizes, int n_in,
                              void* d_out, int out_size)
{
    const float* inp = (const float*)d_in[0];   // input_signal [T, B, S]
    const float* err = (const float*)d_in[1];   // error_signal [T, B, S]
    const float* W   = (const float*)d_in[2];   // W_err [S, S]
    float* out = (float*)d_out;                 // [spks | traces], each T*B*S

    dim3 grid((S_DIM + BN - 1) / BN, M_ROWS / BM);   // (8, 1600)
    gemm_total_kernel<<<grid, 256>>>(inp, err, W);

    scan_kernel<<<(BS + 255) / 256, 256>>>(out, out + (size_t)T_STEPS * BS);
}

// round 5
// speedup vs baseline: 1.2341x; 1.2341x over previous
#include <cuda_runtime.h>

// Problem constants (fixed shapes for SpNCN_Layer_81106162417854)
#define T_STEPS 800
#define BATCH   128
#define S_DIM   500
#define BS      (BATCH * S_DIM)          // 64000
#define M_ROWS  (T_STEPS * BATCH)        // 102400

#define DT     0.25
#define ALPHA_F ((float)(1.0 - DT / 10.0))
#define BETA_F  ((float)(1.0 - DT / 20.0))
#define KAPPA_F ((float)(1.0 - DT / 30.0))
#define THRESH_F 0.4f

// Scratch for total = input - error @ W^T  (205 MB)
__device__ float g_total[(size_t)T_STEPS * BATCH * S_DIM];

// ---------------------------------------------------------------------------
// Kernel 1: total[m,n] = inp[m,n] - sum_k err[m,k] * W[n,k]
// NUMERICS CONTRACT (validated bitwise in R4): per output element, a serial
// ascending-k single-accumulator FFMA chain; final single __fadd_rn subtract.
// 128x128 tile, BK=16 (31 iters) + BK=4 tail, 256 threads, 8x8 per thread
// as 2x2 fragments of 4x4 (float4 LDS), double-buffered smem.
// ---------------------------------------------------------------------------
#define BM 128
#define BN 128
#define BK 16
#define KMAIN 496            // 31 * 16
#define NITER 31

__global__ __launch_bounds__(256, 1) void gemm_total_kernel(
    const float* __restrict__ inp,
    const float* __restrict__ err,
    const float* __restrict__ W)
{
    __shared__ float As[2][BK][BM];   // As[buf][k][m]
    __shared__ float Bs[2][BK][BN];   // Bs[buf][k][n]

    const int bm = blockIdx.y * BM;
    const int bn = blockIdx.x * BN;
    const int t  = threadIdx.x;

    // ---- load mapping: 128 rows x 4 k-quads per operand, 2 quads/thread ----
    const int lrow = t & 127;         // tile row (m for A, n for B)
    const int lq   = t >> 7;          // 0 or 1; quads {lq, lq+2}

    const float* Ap = err + (size_t)(bm + lrow) * S_DIM;
    const int    bn_row = bn + lrow;
    const bool   bok = (bn_row < S_DIM);
    const float* Bp = W + (size_t)(bok ? bn_row : 0) * S_DIM;
    const float4 f4z = make_float4(0.f, 0.f, 0.f, 0.f);

    // ---- compute mapping: cx,ry in 0..15; fragments at +0 and +64 ----
    const int cx = t & 15;
    const int ry = t >> 4;
    const int r0 = ry * 4, r1 = ry * 4 + 64;
    const int c0 = cx * 4, c1 = cx * 4 + 64;

    float acc[8][8];
#pragma unroll
    for (int i = 0; i < 8; i++)
#pragma unroll
        for (int j = 0; j < 8; j++) acc[i][j] = 0.f;

    float4 pa[2], pb[2];

    // prime tile 0
#pragma unroll
    for (int q = 0; q < 2; q++) {
        const int qq = lq + 2 * q;
        pa[q] = *(const float4*)(Ap + qq * 4);
        pb[q] = bok ? *(const float4*)(Bp + qq * 4) : f4z;
    }
#pragma unroll
    for (int q = 0; q < 2; q++) {
        const int qq = lq + 2 * q;
        As[0][qq * 4 + 0][lrow] = pa[q].x;  As[0][qq * 4 + 1][lrow] = pa[q].y;
        As[0][qq * 4 + 2][lrow] = pa[q].z;  As[0][qq * 4 + 3][lrow] = pa[q].w;
        Bs[0][qq * 4 + 0][lrow] = pb[q].x;  Bs[0][qq * 4 + 1][lrow] = pb[q].y;
        Bs[0][qq * 4 + 2][lrow] = pb[q].z;  Bs[0][qq * 4 + 3][lrow] = pb[q].w;
    }
    __syncthreads();

    int cur = 0;
    for (int iter = 0; iter < NITER; iter++) {
        // prefetch next tile to registers
        if (iter < NITER - 1) {
            const int k0n = (iter + 1) * BK;
#pragma unroll
            for (int q = 0; q < 2; q++) {
                const int qq = lq + 2 * q;
                pa[q] = *(const float4*)(Ap + k0n + qq * 4);
                pb[q] = bok ? *(const float4*)(Bp + k0n + qq * 4) : f4z;
            }
        }

        // compute current tile
#pragma unroll
        for (int kk = 0; kk < BK; kk++) {
            float4 a0 = *(const float4*)&As[cur][kk][r0];
            float4 a1 = *(const float4*)&As[cur][kk][r1];
            float4 b0 = *(const float4*)&Bs[cur][kk][c0];
            float4 b1 = *(const float4*)&Bs[cur][kk][c1];
            const float av[8] = {a0.x, a0.y, a0.z, a0.w, a1.x, a1.y, a1.z, a1.w};
            const float bv[8] = {b0.x, b0.y, b0.z, b0.w, b1.x, b1.y, b1.z, b1.w};
#pragma unroll
            for (int i = 0; i < 8; i++)
#pragma unroll
                for (int j = 0; j < 8; j++)
                    acc[i][j] = __fmaf_rn(av[i], bv[j], acc[i][j]);
        }

        if (iter < NITER - 1) {
            const int nxt = cur ^ 1;
#pragma unroll
            for (int q = 0; q < 2; q++) {
                const int qq = lq + 2 * q;
                As[nxt][qq * 4 + 0][lrow] = pa[q].x;  As[nxt][qq * 4 + 1][lrow] = pa[q].y;
                As[nxt][qq * 4 + 2][lrow] = pa[q].z;  As[nxt][qq * 4 + 3][lrow] = pa[q].w;
                Bs[nxt][qq * 4 + 0][lrow] = pb[q].x;  Bs[nxt][qq * 4 + 1][lrow] = pb[q].y;
                Bs[nxt][qq * 4 + 2][lrow] = pb[q].z;  Bs[nxt][qq * 4 + 3][lrow] = pb[q].w;
            }
            __syncthreads();
            cur = nxt;
        }
    }

    // ---- K tail: k = 496..499 (one float4 per row) ----
    __syncthreads();                           // everyone done reading cur
    if (t < 128) {
        float4 v = *(const float4*)(Ap + KMAIN);
        As[0][0][lrow] = v.x; As[0][1][lrow] = v.y;
        As[0][2][lrow] = v.z; As[0][3][lrow] = v.w;
    } else {
        float4 v = bok ? *(const float4*)(Bp + KMAIN) : f4z;
        Bs[0][0][lrow] = v.x; Bs[0][1][lrow] = v.y;
        Bs[0][2][lrow] = v.z; Bs[0][3][lrow] = v.w;
    }
    __syncthreads();
#pragma unroll
    for (int kk = 0; kk < 4; kk++) {
        float4 a0 = *(const float4*)&As[0][kk][r0];
        float4 a1 = *(const float4*)&As[0][kk][r1];
        float4 b0 = *(const float4*)&Bs[0][kk][c0];
        float4 b1 = *(const float4*)&Bs[0][kk][c1];
        const float av[8] = {a0.x, a0.y, a0.z, a0.w, a1.x, a1.y, a1.z, a1.w};
        const float bv[8] = {b0.x, b0.y, b0.z, b0.w, b1.x, b1.y, b1.z, b1.w};
#pragma unroll
        for (int i = 0; i < 8; i++)
#pragma unroll
            for (int j = 0; j < 8; j++)
                acc[i][j] = __fmaf_rn(av[i], bv[j], acc[i][j]);
    }

    // ---- epilogue: total = inp - acc (single rounded subtract), float4 IO ----
#pragma unroll
    for (int i = 0; i < 8; i++) {
        const int m = bm + (i < 4 ? r0 + i : r1 + (i - 4));
        const float* ip = inp + (size_t)m * S_DIM;
        float* op = g_total + (size_t)m * S_DIM;
#pragma unroll
        for (int jg = 0; jg < 2; jg++) {
            const int n0 = bn + (jg == 0 ? c0 : c1);
            if (n0 < S_DIM) {   // n0 % 4 == 0 and S_DIM % 4 == 0 -> all-or-none
                float4 iv = *(const float4*)(ip + n0);
                float4 ov;
                ov.x = __fadd_rn(iv.x, -acc[i][jg * 4 + 0]);
                ov.y = __fadd_rn(iv.y, -acc[i][jg * 4 + 1]);
                ov.z = __fadd_rn(iv.z, -acc[i][jg * 4 + 2]);
                ov.w = __fadd_rn(iv.w, -acc[i][jg * 4 + 3]);
                *(float4*)(op + n0) = ov;
            }
        }
    }
}

// ---------------------------------------------------------------------------
// Kernel 2: sequential scan over T per (b,s) neuron. FMA-contracted math
// (validated bitwise in R4). Batch-16 streaming loads for MLP.
// ---------------------------------------------------------------------------
__global__ __launch_bounds__(256) void scan_kernel(
    float* __restrict__ spk_out,
    float* __restrict__ tr_out)
{
    const int idx = blockIdx.x * blockDim.x + threadIdx.x;
    if (idx >= BS) return;

    const float* tp = g_total + idx;
    float* sp = spk_out + idx;
    float* rp = tr_out + idx;

    float syn = 0.f, mem = 0.f, trace = 0.f;

#pragma unroll 1
    for (int t0 = 0; t0 < T_STEPS; t0 += 16) {
        float tot[16];
#pragma unroll
        for (int i = 0; i < 16; i++)
            tot[i] = __ldcs(tp + (size_t)(t0 + i) * BS);   // streaming, MLP=16

#pragma unroll
        for (int i = 0; i < 16; i++) {
            const float reset = (__fadd_rn(mem, -THRESH_F) > 0.f) ? 1.f : 0.f;
            syn = __fmaf_rn(ALPHA_F, syn, tot[i]);
            mem = __fmul_rn(__fmaf_rn(BETA_F, mem, syn),
                            __fadd_rn(1.f, -reset));
            const float spk = (__fadd_rn(mem, -THRESH_F) > 0.f) ? 1.f : 0.f;
            trace = __fmaf_rn(KAPPA_F, trace, spk);
            __stcs(sp + (size_t)(t0 + i) * BS, spk);
            __stcs(rp + (size_t)(t0 + i) * BS, trace);
        }
    }
}

// ---------------------------------------------------------------------------
extern "C" void kernel_launch(void* const* d_in, const int* in_sizes, int n_in,
                              void* d_out, int out_size)
{
    const float* inp = (const float*)d_in[0];   // input_signal [T, B, S]
    const float* err = (const float*)d_in[1];   // error_signal [T, B, S]
    const float* W   = (const float*)d_in[2];   // W_err [S, S]
    float* out = (float*)d_out;                 // [spks | traces]

    dim3 grid((S_DIM + BN - 1) / BN, M_ROWS / BM);   // (4, 800)
    gemm_total_kernel<<<grid, 256>>>(inp, err, W);

    scan_kernel<<<(BS + 255) / 256, 256>>>(out, out + (size_t)T_STEPS * BS);
}